// round 1
// baseline (speedup 1.0000x reference)
#include <cuda_runtime.h>
#include <math.h>

#define BB 16
#define CC 512
#define KK 32
#define HWN 4096
#define EPSF 1e-5f
#define NSPLIT 8

// ---------------- scratch (static device globals: no allocation) ----------------
__device__ float g_feats[(size_t)BB * HWN * CC];   // (b, n, c)  134 MB
__device__ float g_assign[(size_t)BB * HWN * KK];  // (b, n, k)  8 MB
__device__ float g_x2[BB * HWN];                   // per-pixel ||feats||^2
__device__ float g_enc[BB * KK * CC];              // partial encoded
__device__ float g_asum[BB * KK];                  // sum_n assign
__device__ float g_gamma[BB * CC];

// ---------------- K0: zero scratch ----------------
__global__ void k0_init() {
    int i = blockIdx.x * blockDim.x + threadIdx.x;
    if (i < BB * KK * CC) g_enc[i] = 0.f;
    if (i < BB * HWN)     g_x2[i] = 0.f;
    if (i < BB * KK)      g_asum[i] = 0.f;
}

// ---------------- K1: proj = relu(BN2(conv_w @ x)), store (b,n,c); accumulate x2 ----------------
__global__ void __launch_bounds__(256) k1_proj(
    const float* __restrict__ x, const float* __restrict__ w,
    const float* __restrict__ g2, const float* __restrict__ b2,
    const float* __restrict__ m2, const float* __restrict__ v2)
{
    __shared__ float As[16][128];
    __shared__ float Bs[16][132];
    int tid = threadIdx.x;
    int tx = tid & 15, ty = tid >> 4;
    int m0 = blockIdx.y * 128;          // global pixel-row base (b*HWN + n)
    int o0 = blockIdx.x * 128;          // output-channel base
    int b  = m0 >> 12;                  // / 4096
    int n0 = m0 & (HWN - 1);
    const float* xb = x + (size_t)b * CC * HWN;

    float acc[8][8];
#pragma unroll
    for (int i = 0; i < 8; i++)
#pragma unroll
        for (int j = 0; j < 8; j++) acc[i][j] = 0.f;

    for (int k0 = 0; k0 < CC; k0 += 16) {
        // A tile: x[b][k][n] -> As[k][m], coalesced along n
#pragma unroll
        for (int i = 0; i < 8; i++) {
            int idx = tid + i * 256;
            int kk = idx >> 7, mm = idx & 127;
            As[kk][mm] = xb[(size_t)(k0 + kk) * HWN + n0 + mm];
        }
        // B tile: conv_w[o][k] -> Bs[k][o], vector loads along k
        {
            int oo = tid & 127;
            int half = tid >> 7;
            const float* wr = w + (size_t)(o0 + oo) * CC + k0 + half * 8;
            float4 v0 = *(const float4*)wr;
            float4 v1 = *(const float4*)(wr + 4);
            int kb = half * 8;
            Bs[kb + 0][oo] = v0.x; Bs[kb + 1][oo] = v0.y;
            Bs[kb + 2][oo] = v0.z; Bs[kb + 3][oo] = v0.w;
            Bs[kb + 4][oo] = v1.x; Bs[kb + 5][oo] = v1.y;
            Bs[kb + 6][oo] = v1.z; Bs[kb + 7][oo] = v1.w;
        }
        __syncthreads();
#pragma unroll
        for (int kk = 0; kk < 16; kk++) {
            float ra[8], rb[8];
#pragma unroll
            for (int i = 0; i < 8; i++) ra[i] = As[kk][ty * 8 + i];
#pragma unroll
            for (int j = 0; j < 8; j++) rb[j] = Bs[kk][tx * 8 + j];
#pragma unroll
            for (int i = 0; i < 8; i++)
#pragma unroll
                for (int j = 0; j < 8; j++)
                    acc[i][j] = fmaf(ra[i], rb[j], acc[i][j]);
        }
        __syncthreads();
    }

    // epilogue: BN2 + relu, write feats (b,n,c), accumulate row ||.||^2
    float s2r[8], sh[8];
#pragma unroll
    for (int j = 0; j < 8; j++) {
        int o = o0 + tx * 8 + j;
        float s = rsqrtf(v2[o] + EPSF) * g2[o];
        s2r[j] = s;
        sh[j] = b2[o] - m2[o] * s;
    }
#pragma unroll
    for (int i = 0; i < 8; i++) {
        int n = n0 + ty * 8 + i;
        float* dst = &g_feats[((size_t)b * HWN + n) * CC + o0 + tx * 8];
        float v[8];
        float rq = 0.f;
#pragma unroll
        for (int j = 0; j < 8; j++) {
            float t = fmaf(acc[i][j], s2r[j], sh[j]);
            t = fmaxf(t, 0.f);
            v[j] = t;
            rq = fmaf(t, t, rq);
        }
        *(float4*)dst       = make_float4(v[0], v[1], v[2], v[3]);
        *(float4*)(dst + 4) = make_float4(v[4], v[5], v[6], v[7]);
#pragma unroll
        for (int off = 8; off >= 1; off >>= 1)
            rq += __shfl_xor_sync(0xffffffffu, rq, off);
        if (tx == 0) atomicAdd(&g_x2[b * HWN + n], rq);
    }
}

// ---------------- K2: xc GEMM (128px x 32codes) + fused scaled-L2 softmax -> assign ----------------
__global__ void __launch_bounds__(256) k2_assign(
    const float* __restrict__ cw, const float* __restrict__ scale)
{
    __shared__ float Fs[128][33];
    __shared__ float Cs[32][33];
    __shared__ float c2s[32];
    __shared__ float x2s[128];
    __shared__ float scs[32];
    int tid = threadIdx.x;
    int m0 = blockIdx.x * 128;          // global pixel base

    // c2[k] = ||codewords[k]||^2  (8 lanes per k, 64 elems each)
    {
        int k = tid >> 3, seg = tid & 7;
        const float* p = cw + k * CC + seg * 64;
        float s = 0.f;
#pragma unroll 16
        for (int i = 0; i < 64; i++) { float v = p[i]; s = fmaf(v, v, s); }
#pragma unroll
        for (int off = 4; off >= 1; off >>= 1)
            s += __shfl_xor_sync(0xffffffffu, s, off);
        if (seg == 0) c2s[k] = s;
        if (tid < 32) scs[tid] = scale[tid];
        if (tid < 128) x2s[tid] = g_x2[m0 + tid];
    }

    int kg = tid & 7;    // code group (4 codes)
    int pg = tid >> 3;   // pixel group (4 pixels)
    float acc[4][4];
#pragma unroll
    for (int i = 0; i < 4; i++)
#pragma unroll
        for (int j = 0; j < 4; j++) acc[i][j] = 0.f;

    for (int c0 = 0; c0 < CC; c0 += 32) {
        // feats tile 128x32
#pragma unroll
        for (int i = 0; i < 4; i++) {
            int idx4 = tid + i * 256;
            int p = idx4 >> 3, c4 = idx4 & 7;
            float4 v = *(const float4*)&g_feats[((size_t)(m0 + p)) * CC + c0 + c4 * 4];
            Fs[p][c4 * 4 + 0] = v.x; Fs[p][c4 * 4 + 1] = v.y;
            Fs[p][c4 * 4 + 2] = v.z; Fs[p][c4 * 4 + 3] = v.w;
        }
        // codeword tile 32x32
        {
            int k = tid >> 3, c4 = tid & 7;
            float4 v = *(const float4*)&cw[(size_t)k * CC + c0 + c4 * 4];
            Cs[k][c4 * 4 + 0] = v.x; Cs[k][c4 * 4 + 1] = v.y;
            Cs[k][c4 * 4 + 2] = v.z; Cs[k][c4 * 4 + 3] = v.w;
        }
        __syncthreads();
#pragma unroll 8
        for (int ccv = 0; ccv < 32; ccv++) {
            float rf[4], rc[4];
#pragma unroll
            for (int i = 0; i < 4; i++) rf[i] = Fs[pg * 4 + i][ccv];
#pragma unroll
            for (int j = 0; j < 4; j++) rc[j] = Cs[kg * 4 + j][ccv];
#pragma unroll
            for (int i = 0; i < 4; i++)
#pragma unroll
                for (int j = 0; j < 4; j++)
                    acc[i][j] = fmaf(rf[i], rc[j], acc[i][j]);
        }
        __syncthreads();
    }

    // dist + softmax over k (split across 8 lanes of the warp)
#pragma unroll
    for (int i = 0; i < 4; i++) {
        int p = pg * 4 + i;
        float x2v = x2s[p];
        float d[4];
        float mx = -1e30f;
#pragma unroll
        for (int j = 0; j < 4; j++) {
            int k = kg * 4 + j;
            d[j] = scs[k] * (x2v - 2.f * acc[i][j] + c2s[k]);
            mx = fmaxf(mx, d[j]);
        }
#pragma unroll
        for (int off = 4; off >= 1; off >>= 1)
            mx = fmaxf(mx, __shfl_xor_sync(0xffffffffu, mx, off));
        float se = 0.f;
#pragma unroll
        for (int j = 0; j < 4; j++) { d[j] = __expf(d[j] - mx); se += d[j]; }
#pragma unroll
        for (int off = 4; off >= 1; off >>= 1)
            se += __shfl_xor_sync(0xffffffffu, se, off);
        float inv = 1.f / se;
        *(float4*)&g_assign[((size_t)(m0 + p)) * KK + kg * 4] =
            make_float4(d[0] * inv, d[1] * inv, d[2] * inv, d[3] * inv);
    }
}

// ---------------- K3: encoded_part = assign^T @ feats (n-split, atomic acc) + asum ----------------
__global__ void __launch_bounds__(256) k3_agg()
{
    __shared__ float Ws[32][33];     // assign tile
    __shared__ float Fs[32][132];    // feats tile (row = 528B, 16B aligned)
    int tid = threadIdx.x;
    int b  = blockIdx.z;
    int c0 = blockIdx.x * 128;
    int n0 = blockIdx.y * (HWN / NSPLIT);
    int m0 = b * HWN + n0;
    int kg = tid >> 5;   // warp id = code group
    int cg = tid & 31;   // lane = channel group

    float acc[4][4];
#pragma unroll
    for (int j = 0; j < 4; j++)
#pragma unroll
        for (int l = 0; l < 4; l++) acc[j][l] = 0.f;
    float asumr[4] = {0.f, 0.f, 0.f, 0.f};

    for (int nt = 0; nt < HWN / NSPLIT; nt += 32) {
        {
            int nn = tid >> 3, kq = tid & 7;
            float4 v = *(const float4*)&g_assign[((size_t)(m0 + nt + nn)) * KK + kq * 4];
            Ws[nn][kq * 4 + 0] = v.x; Ws[nn][kq * 4 + 1] = v.y;
            Ws[nn][kq * 4 + 2] = v.z; Ws[nn][kq * 4 + 3] = v.w;
        }
#pragma unroll
        for (int i = 0; i < 4; i++) {
            int idx4 = tid + i * 256;
            int nn = idx4 >> 5, c4 = idx4 & 31;
            float4 v = *(const float4*)&g_feats[((size_t)(m0 + nt + nn)) * CC + c0 + c4 * 4];
            *(float4*)&Fs[nn][c4 * 4] = v;
        }
        __syncthreads();
#pragma unroll 4
        for (int nn = 0; nn < 32; nn++) {
            float w0 = Ws[nn][kg * 4 + 0];
            float w1 = Ws[nn][kg * 4 + 1];
            float w2 = Ws[nn][kg * 4 + 2];
            float w3 = Ws[nn][kg * 4 + 3];
            float4 f = *(const float4*)&Fs[nn][cg * 4];
            acc[0][0] = fmaf(w0, f.x, acc[0][0]); acc[0][1] = fmaf(w0, f.y, acc[0][1]);
            acc[0][2] = fmaf(w0, f.z, acc[0][2]); acc[0][3] = fmaf(w0, f.w, acc[0][3]);
            acc[1][0] = fmaf(w1, f.x, acc[1][0]); acc[1][1] = fmaf(w1, f.y, acc[1][1]);
            acc[1][2] = fmaf(w1, f.z, acc[1][2]); acc[1][3] = fmaf(w1, f.w, acc[1][3]);
            acc[2][0] = fmaf(w2, f.x, acc[2][0]); acc[2][1] = fmaf(w2, f.y, acc[2][1]);
            acc[2][2] = fmaf(w2, f.z, acc[2][2]); acc[2][3] = fmaf(w2, f.w, acc[2][3]);
            acc[3][0] = fmaf(w3, f.x, acc[3][0]); acc[3][1] = fmaf(w3, f.y, acc[3][1]);
            acc[3][2] = fmaf(w3, f.z, acc[3][2]); acc[3][3] = fmaf(w3, f.w, acc[3][3]);
            if (cg == 0) {
                asumr[0] += w0; asumr[1] += w1; asumr[2] += w2; asumr[3] += w3;
            }
        }
        __syncthreads();
    }

    int cbase = c0 + cg * 4;
#pragma unroll
    for (int j = 0; j < 4; j++) {
        int k = kg * 4 + j;
        float* dst = &g_enc[((size_t)b * KK + k) * CC + cbase];
        atomicAdd(dst + 0, acc[j][0]);
        atomicAdd(dst + 1, acc[j][1]);
        atomicAdd(dst + 2, acc[j][2]);
        atomicAdd(dst + 3, acc[j][3]);
    }
    if (cg == 0 && blockIdx.x == 0) {
#pragma unroll
        for (int j = 0; j < 4; j++)
            atomicAdd(&g_asum[b * KK + kg * 4 + j], asumr[j]);
    }
}

// ---------------- K4: encoded -= asum*cw; BN1+relu; mean over k -> encoding_feat ----------------
__global__ void k4_ef(
    const float* __restrict__ cw, const float* __restrict__ g1,
    const float* __restrict__ b1, const float* __restrict__ m1,
    const float* __restrict__ v1, float* __restrict__ ef_out)
{
    int b = blockIdx.y;
    int c = blockIdx.x * 128 + threadIdx.x;
    float s = 0.f;
#pragma unroll
    for (int k = 0; k < KK; k++) {
        float e = g_enc[((size_t)b * KK + k) * CC + c] - g_asum[b * KK + k] * cw[(size_t)k * CC + c];
        float sc = rsqrtf(v1[k] + EPSF) * g1[k];
        e = fmaf(e - m1[k], sc, b1[k]);
        e = fmaxf(e, 0.f);
        s += e;
    }
    ef_out[b * CC + c] = s * (1.f / KK);
}

// ---------------- K5: gamma = sigmoid(ef @ fc_w^T + fc_b) ----------------
__global__ void __launch_bounds__(512) k5_gamma(
    const float* __restrict__ fcw, const float* __restrict__ fcb,
    const float* __restrict__ ef)
{
    __shared__ float efs[CC];
    int b = blockIdx.x;
    int o = threadIdx.x;
    efs[o] = ef[b * CC + o];
    __syncthreads();
    const float* wr = fcw + (size_t)o * CC;
    float s = fcb[o];
#pragma unroll 8
    for (int c = 0; c < CC; c += 4) {
        float4 w4 = *(const float4*)&wr[c];
        s = fmaf(w4.x, efs[c + 0], s);
        s = fmaf(w4.y, efs[c + 1], s);
        s = fmaf(w4.z, efs[c + 2], s);
        s = fmaf(w4.w, efs[c + 3], s);
    }
    g_gamma[b * CC + o] = 1.f / (1.f + __expf(-s));
}

// ---------------- K6: output = relu(x * (1 + gamma)) ----------------
__global__ void __launch_bounds__(256) k6_out(
    const float* __restrict__ x, float* __restrict__ out)
{
    size_t i4 = (size_t)blockIdx.x * blockDim.x + threadIdx.x;
    size_t total4 = (size_t)BB * CC * HWN / 4;
    if (i4 >= total4) return;
    size_t i = i4 * 4;
    int bc = (int)(i >> 12);                 // i / HWN = b*CC + c
    float g = 1.f + g_gamma[bc];
    float4 v = *(const float4*)&x[i];
    v.x = fmaxf(v.x * g, 0.f);
    v.y = fmaxf(v.y * g, 0.f);
    v.z = fmaxf(v.z * g, 0.f);
    v.w = fmaxf(v.w * g, 0.f);
    *(float4*)&out[i] = v;
}

// ---------------- launch ----------------
extern "C" void kernel_launch(void* const* d_in, const int* in_sizes, int n_in,
                              void* d_out, int out_size)
{
    const float* x      = (const float*)d_in[0];
    const float* conv_w = (const float*)d_in[1];
    const float* bn2_g  = (const float*)d_in[2];
    const float* bn2_b  = (const float*)d_in[3];
    const float* bn2_m  = (const float*)d_in[4];
    const float* bn2_v  = (const float*)d_in[5];
    const float* cw     = (const float*)d_in[6];
    const float* scale  = (const float*)d_in[7];
    const float* bn1_g  = (const float*)d_in[8];
    const float* bn1_b  = (const float*)d_in[9];
    const float* bn1_m  = (const float*)d_in[10];
    const float* bn1_v  = (const float*)d_in[11];
    const float* fc_w   = (const float*)d_in[12];
    const float* fc_b   = (const float*)d_in[13];
    float* out = (float*)d_out;   // [0:8192) encoding_feat, [8192:) output

    k0_init<<<1024, 256>>>();

    dim3 g1(CC / 128, BB * HWN / 128);   // (4, 512)
    k1_proj<<<g1, 256>>>(x, conv_w, bn2_g, bn2_b, bn2_m, bn2_v);

    k2_assign<<<BB * HWN / 128, 256>>>(cw, scale);

    dim3 g3(CC / 128, NSPLIT, BB);       // (4, 8, 16)
    k3_agg<<<g3, 256>>>();

    dim3 g4(CC / 128, BB);               // (4, 16)
    k4_ef<<<g4, 128>>>(cw, bn1_g, bn1_b, bn1_m, bn1_v, out);

    k5_gamma<<<BB, 512>>>(fc_w, fc_b, out);

    k6_out<<<(BB * CC * HWN / 4 + 255) / 256, 256>>>(x, out + BB * CC);
}

// round 5
// speedup vs baseline: 1.6824x; 1.6824x over previous
#include <cuda_runtime.h>
#include <cuda_bf16.h>
#include <cstdint>
#include <math.h>

#define BB 16
#define CC 512
#define KK 32
#define HWN 4096
#define EPSF 1e-5f
#define NSPLIT 8

// ---------------- scratch (static device globals: no allocation) ----------------
__device__ float g_feats[(size_t)BB * HWN * CC];   // (b, n, c)  134 MB
__device__ float g_assign[(size_t)BB * HWN * KK];  // (b, n, k)  8 MB
__device__ float g_x2[BB * HWN];                   // per-pixel ||feats||^2
__device__ float g_enc[BB * KK * CC];              // partial encoded
__device__ float g_asum[BB * KK];                  // sum_n assign
__device__ float g_gamma[BB * CC];
__device__ __nv_bfloat16 g_xhi[(size_t)BB * HWN * CC];  // x^T (b,n,c) bf16 hi
__device__ __nv_bfloat16 g_xlo[(size_t)BB * HWN * CC];  // x^T (b,n,c) bf16 lo
__device__ __nv_bfloat16 g_whi[CC * CC];
__device__ __nv_bfloat16 g_wlo[CC * CC];

// ---------------- helpers (baseline PTX only: sm_80-era, valid at compute_103) ----------------
__device__ __forceinline__ uint32_t smem_u32(const void* p) {
    uint32_t a;
    asm("{ .reg .u64 t; cvta.to.shared.u64 t, %1; cvt.u32.u64 %0, t; }" : "=r"(a) : "l"(p));
    return a;
}
__device__ __forceinline__ uint32_t swz(uint32_t o) { return o ^ ((o >> 3) & 0x70); }

__device__ __forceinline__ void cpasync16(uint32_t dst, const void* src) {
    asm volatile("cp.async.cg.shared.global [%0], [%1], 16;"
                 :: "r"(dst), "l"(__cvta_generic_to_global(src)) : "memory");
}
#define CP_COMMIT() asm volatile("cp.async.commit_group;" ::: "memory")
#define CP_WAIT2()  asm volatile("cp.async.wait_group 2;" ::: "memory")

__device__ __forceinline__ void ldsm4(uint32_t addr, uint32_t* r) {
    asm volatile("ldmatrix.sync.aligned.m8n8.x4.shared.b16 {%0,%1,%2,%3}, [%4];"
                 : "=r"(r[0]), "=r"(r[1]), "=r"(r[2]), "=r"(r[3]) : "r"(addr));
}
__device__ __forceinline__ void mma_bf16(float* c, const uint32_t* a, uint32_t b0, uint32_t b1) {
    asm volatile(
        "mma.sync.aligned.m16n8k16.row.col.f32.bf16.bf16.f32 "
        "{%0,%1,%2,%3}, {%4,%5,%6,%7}, {%8,%9}, {%0,%1,%2,%3};"
        : "+f"(c[0]), "+f"(c[1]), "+f"(c[2]), "+f"(c[3])
        : "r"(a[0]), "r"(a[1]), "r"(a[2]), "r"(a[3]), "r"(b0), "r"(b1));
}

// ---------------- K_pre_w: conv_w -> bf16 hi/lo ----------------
__global__ void kpw(const float* __restrict__ w) {
    int i = blockIdx.x * blockDim.x + threadIdx.x;
    if (i < CC * CC) {
        float v = w[i];
        __nv_bfloat16 h = __float2bfloat16(v);
        g_whi[i] = h;
        g_wlo[i] = __float2bfloat16(v - __bfloat162float(h));
    }
}

// ---------------- K_pre_x: transpose x (b,c,n)->(b,n,c) + split bf16 hi/lo ----------------
__global__ void __launch_bounds__(256) kpx(const float* __restrict__ x) {
    __shared__ float t[32][33];
    int tx = threadIdx.x, ty = threadIdx.y;
    int b = blockIdx.z;
    int cb = blockIdx.y * 32;
    int nb = blockIdx.x * 32;
    const float* xb = x + (size_t)b * CC * HWN;
#pragma unroll
    for (int i = ty; i < 32; i += 8)
        t[i][tx] = xb[(size_t)(cb + i) * HWN + nb + tx];
    __syncthreads();
#pragma unroll
    for (int i = ty; i < 32; i += 8) {
        float v = t[tx][i];
        __nv_bfloat16 h = __float2bfloat16(v);
        size_t o = ((size_t)b * HWN + nb + i) * CC + cb + tx;
        g_xhi[o] = h;
        g_xlo[o] = __float2bfloat16(v - __bfloat162float(h));
    }
}

// ---------------- K0: zero scratch ----------------
__global__ void k0_init() {
    int i = blockIdx.x * blockDim.x + threadIdx.x;
    if (i < BB * KK * CC) g_enc[i] = 0.f;
    if (i < BB * HWN)     g_x2[i] = 0.f;
    if (i < BB * KK)      g_asum[i] = 0.f;
}

// ---------------- K1: HMMA split-bf16 GEMM + BN2 + relu -> feats, x2 ----------------
// CTA: 128 px (M) x 128 ch (N), 8 warps in 4(m) x 2(n), warp tile 32x64.
// K-chunks of 64, 3-stage cp.async pipeline.
// Stage layout (64 KB each): Xhi[128x128B] Xlo Whi Wlo at +0,+16K,+32K,+48K.
#define K1_STAGE  65536
#define K1_TILES  1024
#define SMEM_K1M  (K1_TILES + 3 * K1_STAGE)

__global__ void __launch_bounds__(256, 1) k1_mma(
    const float* __restrict__ g2, const float* __restrict__ b2,
    const float* __restrict__ m2, const float* __restrict__ v2)
{
    extern __shared__ char sm[];
    uint32_t sb = smem_u32(sm);
    int tid = threadIdx.x;
    int lane = tid & 31;
    int wid = tid >> 5;
    int warp_m = wid >> 1;       // 0..3
    int warp_n = wid & 1;        // 0..1
    int n0 = blockIdx.x * 128;   // output-channel base
    int m0 = blockIdx.y * 128;   // pixel base (b*HWN + n)

    float* bns = (float*)sm;
    float* bnh = (float*)(sm + 512);
    if (tid < 128) {
        int o = n0 + tid;
        float s = rsqrtf(v2[o] + EPSF) * g2[o];
        bns[tid] = s;
        bnh[tid] = b2[o] - m2[o] * s;
    }

    const __nv_bfloat16* xh = g_xhi + (size_t)m0 * CC;
    const __nv_bfloat16* xl = g_xlo + (size_t)m0 * CC;
    const __nv_bfloat16* wh = g_whi + (size_t)n0 * CC;
    const __nv_bfloat16* wl = g_wlo + (size_t)n0 * CC;

    auto issue_stage = [&](int s) {
        uint32_t base = sb + K1_TILES + (s % 3) * K1_STAGE;
        int k0 = s * 64;
#pragma unroll
        for (int it = 0; it < 4; it++) {
            int idx = tid + it * 256;
            int row = idx >> 3, seg = idx & 7;
            uint32_t d = swz((uint32_t)(row * 128 + seg * 16));
            size_t go = (size_t)row * CC + k0 + seg * 8;
            cpasync16(base + d,         xh + go);
            cpasync16(base + 16384 + d, xl + go);
            cpasync16(base + 32768 + d, wh + go);
            cpasync16(base + 49152 + d, wl + go);
        }
    };

    issue_stage(0); CP_COMMIT();
    issue_stage(1); CP_COMMIT();
    issue_stage(2); CP_COMMIT();

    float c[2][8][4];
#pragma unroll
    for (int i = 0; i < 2; i++)
#pragma unroll
        for (int j = 0; j < 8; j++)
#pragma unroll
            for (int l = 0; l < 4; l++) c[i][j][l] = 0.f;

    for (int s = 0; s < 8; s++) {
        CP_WAIT2();
        __syncthreads();
        uint32_t tb = sb + K1_TILES + (s % 3) * K1_STAGE;
#pragma unroll
        for (int kk = 0; kk < 4; kk++) {
            uint32_t ah[2][4], al[2][4];
#pragma unroll
            for (int mt = 0; mt < 2; mt++) {
                uint32_t off = (uint32_t)((warp_m * 32 + mt * 16 + (lane & 15)) * 128
                                          + kk * 32 + (lane >> 4) * 16);
                off = swz(off);
                ldsm4(tb + off, ah[mt]);
                ldsm4(tb + 16384 + off, al[mt]);
            }
            uint32_t bh[4][4], bl[4][4];
#pragma unroll
            for (int ng = 0; ng < 4; ng++) {
                uint32_t off = (uint32_t)((warp_n * 64 + ng * 16 + (lane & 15)) * 128
                                          + kk * 32 + (lane >> 4) * 16);
                off = swz(off);
                ldsm4(tb + 32768 + off, bh[ng]);
                ldsm4(tb + 49152 + off, bl[ng]);
            }
            // ldmatrix.x4 on B returns: [n0-7,k0-7], [n8-15,k0-7], [n0-7,k8-15], [n8-15,k8-15]
            // mma n8-slice h needs {b0,b1} = {regs h, h+2} (same n-range, k halves)
#pragma unroll
            for (int mt = 0; mt < 2; mt++)
#pragma unroll
                for (int ng = 0; ng < 4; ng++)
#pragma unroll
                    for (int h = 0; h < 2; h++) {
                        float* cc = c[mt][ng * 2 + h];
                        mma_bf16(cc, ah[mt], bh[ng][h], bh[ng][h + 2]);
                        mma_bf16(cc, ah[mt], bl[ng][h], bl[ng][h + 2]);
                        mma_bf16(cc, al[mt], bh[ng][h], bh[ng][h + 2]);
                    }
        }
        __syncthreads();
        if (s + 3 < 8) issue_stage(s + 3);
        CP_COMMIT();
    }

    // epilogue: BN2 + relu -> g_feats, x2 partials via quad shuffle + atomics
#pragma unroll
    for (int mt = 0; mt < 2; mt++) {
        int r0 = m0 + warp_m * 32 + mt * 16 + (lane >> 2);
        float q0 = 0.f, q1 = 0.f;
#pragma unroll
        for (int j = 0; j < 8; j++) {
            int cl = warp_n * 64 + j * 8 + (lane & 3) * 2;
            float s0 = bns[cl], h0 = bnh[cl];
            float s1 = bns[cl + 1], h1 = bnh[cl + 1];
            float v00 = fmaxf(fmaf(c[mt][j][0], s0, h0), 0.f);
            float v01 = fmaxf(fmaf(c[mt][j][1], s1, h1), 0.f);
            float v10 = fmaxf(fmaf(c[mt][j][2], s0, h0), 0.f);
            float v11 = fmaxf(fmaf(c[mt][j][3], s1, h1), 0.f);
            *(float2*)&g_feats[(size_t)r0 * CC + n0 + cl] = make_float2(v00, v01);
            *(float2*)&g_feats[(size_t)(r0 + 8) * CC + n0 + cl] = make_float2(v10, v11);
            q0 = fmaf(v00, v00, fmaf(v01, v01, q0));
            q1 = fmaf(v10, v10, fmaf(v11, v11, q1));
        }
        q0 += __shfl_xor_sync(0xffffffffu, q0, 1);
        q0 += __shfl_xor_sync(0xffffffffu, q0, 2);
        q1 += __shfl_xor_sync(0xffffffffu, q1, 1);
        q1 += __shfl_xor_sync(0xffffffffu, q1, 2);
        if ((lane & 3) == 0) {
            atomicAdd(&g_x2[r0], q0);
            atomicAdd(&g_x2[r0 + 8], q1);
        }
    }
}

// ---------------- K2: xc GEMM (128px x 32codes) + fused scaled-L2 softmax -> assign ----------------
__global__ void __launch_bounds__(256) k2_assign(
    const float* __restrict__ cw, const float* __restrict__ scale)
{
    __shared__ float Fs[128][33];
    __shared__ float Cs[32][33];
    __shared__ float c2s[32];
    __shared__ float x2s[128];
    __shared__ float scs[32];
    int tid = threadIdx.x;
    int m0 = blockIdx.x * 128;

    {
        int k = tid >> 3, seg = tid & 7;
        const float* p = cw + k * CC + seg * 64;
        float s = 0.f;
#pragma unroll 16
        for (int i = 0; i < 64; i++) { float v = p[i]; s = fmaf(v, v, s); }
#pragma unroll
        for (int off = 4; off >= 1; off >>= 1)
            s += __shfl_xor_sync(0xffffffffu, s, off);
        if (seg == 0) c2s[k] = s;
        if (tid < 32) scs[tid] = scale[tid];
        if (tid < 128) x2s[tid] = g_x2[m0 + tid];
    }

    int kg = tid & 7;
    int pg = tid >> 3;
    float acc[4][4];
#pragma unroll
    for (int i = 0; i < 4; i++)
#pragma unroll
        for (int j = 0; j < 4; j++) acc[i][j] = 0.f;

    for (int c0 = 0; c0 < CC; c0 += 32) {
#pragma unroll
        for (int i = 0; i < 4; i++) {
            int idx4 = tid + i * 256;
            int p = idx4 >> 3, c4 = idx4 & 7;
            float4 v = *(const float4*)&g_feats[((size_t)(m0 + p)) * CC + c0 + c4 * 4];
            Fs[p][c4 * 4 + 0] = v.x; Fs[p][c4 * 4 + 1] = v.y;
            Fs[p][c4 * 4 + 2] = v.z; Fs[p][c4 * 4 + 3] = v.w;
        }
        {
            int k = tid >> 3, c4 = tid & 7;
            float4 v = *(const float4*)&cw[(size_t)k * CC + c0 + c4 * 4];
            Cs[k][c4 * 4 + 0] = v.x; Cs[k][c4 * 4 + 1] = v.y;
            Cs[k][c4 * 4 + 2] = v.z; Cs[k][c4 * 4 + 3] = v.w;
        }
        __syncthreads();
#pragma unroll 8
        for (int ccv = 0; ccv < 32; ccv++) {
            float rf[4], rc[4];
#pragma unroll
            for (int i = 0; i < 4; i++) rf[i] = Fs[pg * 4 + i][ccv];
#pragma unroll
            for (int j = 0; j < 4; j++) rc[j] = Cs[kg * 4 + j][ccv];
#pragma unroll
            for (int i = 0; i < 4; i++)
#pragma unroll
                for (int j = 0; j < 4; j++)
                    acc[i][j] = fmaf(rf[i], rc[j], acc[i][j]);
        }
        __syncthreads();
    }

#pragma unroll
    for (int i = 0; i < 4; i++) {
        int p = pg * 4 + i;
        float x2v = x2s[p];
        float d[4];
        float mx = -1e30f;
#pragma unroll
        for (int j = 0; j < 4; j++) {
            int k = kg * 4 + j;
            d[j] = scs[k] * (x2v - 2.f * acc[i][j] + c2s[k]);
            mx = fmaxf(mx, d[j]);
        }
#pragma unroll
        for (int off = 4; off >= 1; off >>= 1)
            mx = fmaxf(mx, __shfl_xor_sync(0xffffffffu, mx, off));
        float se = 0.f;
#pragma unroll
        for (int j = 0; j < 4; j++) { d[j] = __expf(d[j] - mx); se += d[j]; }
#pragma unroll
        for (int off = 4; off >= 1; off >>= 1)
            se += __shfl_xor_sync(0xffffffffu, se, off);
        float inv = 1.f / se;
        *(float4*)&g_assign[((size_t)(m0 + p)) * KK + kg * 4] =
            make_float4(d[0] * inv, d[1] * inv, d[2] * inv, d[3] * inv);
    }
}

// ---------------- K3: encoded_part = assign^T @ feats (n-split, atomic acc) + asum ----------------
__global__ void __launch_bounds__(256) k3_agg()
{
    __shared__ float Ws[32][33];
    __shared__ float Fs[32][132];
    int tid = threadIdx.x;
    int b  = blockIdx.z;
    int c0 = blockIdx.x * 128;
    int n0 = blockIdx.y * (HWN / NSPLIT);
    int m0 = b * HWN + n0;
    int kg = tid >> 5;
    int cg = tid & 31;

    float acc[4][4];
#pragma unroll
    for (int j = 0; j < 4; j++)
#pragma unroll
        for (int l = 0; l < 4; l++) acc[j][l] = 0.f;
    float asumr[4] = {0.f, 0.f, 0.f, 0.f};

    for (int nt = 0; nt < HWN / NSPLIT; nt += 32) {
        {
            int nn = tid >> 3, kq = tid & 7;
            float4 v = *(const float4*)&g_assign[((size_t)(m0 + nt + nn)) * KK + kq * 4];
            Ws[nn][kq * 4 + 0] = v.x; Ws[nn][kq * 4 + 1] = v.y;
            Ws[nn][kq * 4 + 2] = v.z; Ws[nn][kq * 4 + 3] = v.w;
        }
#pragma unroll
        for (int i = 0; i < 4; i++) {
            int idx4 = tid + i * 256;
            int nn = idx4 >> 5, c4 = idx4 & 31;
            float4 v = *(const float4*)&g_feats[((size_t)(m0 + nt + nn)) * CC + c0 + c4 * 4];
            *(float4*)&Fs[nn][c4 * 4] = v;
        }
        __syncthreads();
#pragma unroll 4
        for (int nn = 0; nn < 32; nn++) {
            float w0 = Ws[nn][kg * 4 + 0];
            float w1 = Ws[nn][kg * 4 + 1];
            float w2 = Ws[nn][kg * 4 + 2];
            float w3 = Ws[nn][kg * 4 + 3];
            float4 f = *(const float4*)&Fs[nn][cg * 4];
            acc[0][0] = fmaf(w0, f.x, acc[0][0]); acc[0][1] = fmaf(w0, f.y, acc[0][1]);
            acc[0][2] = fmaf(w0, f.z, acc[0][2]); acc[0][3] = fmaf(w0, f.w, acc[0][3]);
            acc[1][0] = fmaf(w1, f.x, acc[1][0]); acc[1][1] = fmaf(w1, f.y, acc[1][1]);
            acc[1][2] = fmaf(w1, f.z, acc[1][2]); acc[1][3] = fmaf(w1, f.w, acc[1][3]);
            acc[2][0] = fmaf(w2, f.x, acc[2][0]); acc[2][1] = fmaf(w2, f.y, acc[2][1]);
            acc[2][2] = fmaf(w2, f.z, acc[2][2]); acc[2][3] = fmaf(w2, f.w, acc[2][3]);
            acc[3][0] = fmaf(w3, f.x, acc[3][0]); acc[3][1] = fmaf(w3, f.y, acc[3][1]);
            acc[3][2] = fmaf(w3, f.z, acc[3][2]); acc[3][3] = fmaf(w3, f.w, acc[3][3]);
            if (cg == 0) {
                asumr[0] += w0; asumr[1] += w1; asumr[2] += w2; asumr[3] += w3;
            }
        }
        __syncthreads();
    }

    int cbase = c0 + cg * 4;
#pragma unroll
    for (int j = 0; j < 4; j++) {
        int k = kg * 4 + j;
        float* dst = &g_enc[((size_t)b * KK + k) * CC + cbase];
        atomicAdd(dst + 0, acc[j][0]);
        atomicAdd(dst + 1, acc[j][1]);
        atomicAdd(dst + 2, acc[j][2]);
        atomicAdd(dst + 3, acc[j][3]);
    }
    if (cg == 0 && blockIdx.x == 0) {
#pragma unroll
        for (int j = 0; j < 4; j++)
            atomicAdd(&g_asum[b * KK + kg * 4 + j], asumr[j]);
    }
}

// ---------------- K4 ----------------
__global__ void k4_ef(
    const float* __restrict__ cw, const float* __restrict__ g1,
    const float* __restrict__ b1, const float* __restrict__ m1,
    const float* __restrict__ v1, float* __restrict__ ef_out)
{
    int b = blockIdx.y;
    int c = blockIdx.x * 128 + threadIdx.x;
    float s = 0.f;
#pragma unroll
    for (int k = 0; k < KK; k++) {
        float e = g_enc[((size_t)b * KK + k) * CC + c] - g_asum[b * KK + k] * cw[(size_t)k * CC + c];
        float sc = rsqrtf(v1[k] + EPSF) * g1[k];
        e = fmaf(e - m1[k], sc, b1[k]);
        e = fmaxf(e, 0.f);
        s += e;
    }
    ef_out[b * CC + c] = s * (1.f / KK);
}

// ---------------- K5 ----------------
__global__ void __launch_bounds__(512) k5_gamma(
    const float* __restrict__ fcw, const float* __restrict__ fcb,
    const float* __restrict__ ef)
{
    __shared__ float efs[CC];
    int b = blockIdx.x;
    int o = threadIdx.x;
    efs[o] = ef[b * CC + o];
    __syncthreads();
    const float* wr = fcw + (size_t)o * CC;
    float s = fcb[o];
#pragma unroll 8
    for (int c = 0; c < CC; c += 4) {
        float4 w4 = *(const float4*)&wr[c];
        s = fmaf(w4.x, efs[c + 0], s);
        s = fmaf(w4.y, efs[c + 1], s);
        s = fmaf(w4.z, efs[c + 2], s);
        s = fmaf(w4.w, efs[c + 3], s);
    }
    g_gamma[b * CC + o] = 1.f / (1.f + __expf(-s));
}

// ---------------- K6 ----------------
__global__ void __launch_bounds__(256) k6_out(
    const float* __restrict__ x, float* __restrict__ out)
{
    size_t i4 = (size_t)blockIdx.x * blockDim.x + threadIdx.x;
    size_t total4 = (size_t)BB * CC * HWN / 4;
    if (i4 >= total4) return;
    size_t i = i4 * 4;
    int bc = (int)(i >> 12);
    float g = 1.f + g_gamma[bc];
    float4 v = *(const float4*)&x[i];
    v.x = fmaxf(v.x * g, 0.f);
    v.y = fmaxf(v.y * g, 0.f);
    v.z = fmaxf(v.z * g, 0.f);
    v.w = fmaxf(v.w * g, 0.f);
    *(float4*)&out[i] = v;
}

// ---------------- launch ----------------
extern "C" void kernel_launch(void* const* d_in, const int* in_sizes, int n_in,
                              void* d_out, int out_size)
{
    const float* x      = (const float*)d_in[0];
    const float* conv_w = (const float*)d_in[1];
    const float* bn2_g  = (const float*)d_in[2];
    const float* bn2_b  = (const float*)d_in[3];
    const float* bn2_m  = (const float*)d_in[4];
    const float* bn2_v  = (const float*)d_in[5];
    const float* cw     = (const float*)d_in[6];
    const float* scale  = (const float*)d_in[7];
    const float* bn1_g  = (const float*)d_in[8];
    const float* bn1_b  = (const float*)d_in[9];
    const float* bn1_m  = (const float*)d_in[10];
    const float* bn1_v  = (const float*)d_in[11];
    const float* fc_w   = (const float*)d_in[12];
    const float* fc_b   = (const float*)d_in[13];
    float* out = (float*)d_out;   // [0:8192) encoding_feat, [8192:) output

    static bool attr_set = false;
    if (!attr_set) {
        cudaFuncSetAttribute(k1_mma, cudaFuncAttributeMaxDynamicSharedMemorySize, SMEM_K1M);
        attr_set = true;
    }

    kpw<<<(CC * CC + 255) / 256, 256>>>(conv_w);

    dim3 gpx(HWN / 32, CC / 32, BB);
    kpx<<<gpx, dim3(32, 8)>>>(x);

    k0_init<<<1024, 256>>>();

    dim3 g1(CC / 128, BB * HWN / 128);   // (4, 512)
    k1_mma<<<g1, 256, SMEM_K1M>>>(bn2_g, bn2_b, bn2_m, bn2_v);

    k2_assign<<<BB * HWN / 128, 256>>>(cw, scale);

    dim3 g3(CC / 128, NSPLIT, BB);
    k3_agg<<<g3, 256>>>();

    dim3 g4(CC / 128, BB);
    k4_ef<<<g4, 128>>>(cw, bn1_g, bn1_b, bn1_m, bn1_v, out);

    k5_gamma<<<BB, 512>>>(fc_w, fc_b, out);

    k6_out<<<(BB * CC * HWN / 4 + 255) / 256, 256>>>(x, out + BB * CC);
}